// round 17
// baseline (speedup 1.0000x reference)
#include <cuda_runtime.h>
#include <cuda_fp16.h>
#include <math.h>
#include <stdint.h>

// Problem constants
#define B_   32
#define SSRC 512
#define D_   512
#define STR_ 4
#define T_   2048
#define V_   512
#define L_   256
#define S_   513
#define SP_  520
#define CH_  8
#define NC_  (T_/CH_)

// -------------------- scratch (device globals) ----------------------------
__device__ __half g_repf[(size_t)16384 * 512];
__device__ __half g_Wexpf[(size_t)512 * 2048];   // Wexp fp16 (no transpose)
__device__ __half g_W1t[(size_t)1024 * 512];     // W1^T fp16
__device__ __half g_W2t[(size_t)512 * 1024];     // W2^T fp16
__device__ __half g_Bc[(size_t)4096 * 512];      // merged weight [nq, e]
__device__ float  g_bc[4096];                     // merged bias
__device__ float  g_zb[512];                      // zero bias (zero-initialized)
__device__ __half g_H[(size_t)65536 * 1024];     // hidden fp16 (== [16384,4096])
__device__ __align__(16) __half g_Pexth[(size_t)B_ * T_ * SP_];
__device__ float g_Msum[B_];
__device__ int   g_tlen[B_];
__device__ int   g_olen[B_];

// -------------------- helpers ---------------------------------------------
__device__ __forceinline__ float warpReduceMaxF(float v) {
#pragma unroll
    for (int o = 16; o > 0; o >>= 1) v = fmaxf(v, __shfl_xor_sync(0xffffffffu, v, o));
    return v;
}
__device__ __forceinline__ float warpReduceSumF(float v) {
#pragma unroll
    for (int o = 16; o > 0; o >>= 1) v += __shfl_xor_sync(0xffffffffu, v, o);
    return v;
}
__device__ __forceinline__ int warpReduceSumI(int v) {
#pragma unroll
    for (int o = 16; o > 0; o >>= 1) v += __shfl_xor_sync(0xffffffffu, v, o);
    return v;
}
__device__ __forceinline__ uint32_t smem_u32(const void* p) {
    uint32_t a;
    asm("{ .reg .u64 t; cvta.to.shared.u64 t, %1; cvt.u32.u64 %0, t; }" : "=r"(a) : "l"(p));
    return a;
}
__device__ __forceinline__ uint32_t swz128(uint32_t x) { return x ^ ((x >> 3) & 0x70u); }

__device__ __forceinline__ void cpa16(uint32_t dst, const void* src) {
    asm volatile("cp.async.cg.shared.global [%0], [%1], 16;" :: "r"(dst), "l"(src));
}
#define CP_COMMIT() asm volatile("cp.async.commit_group;" ::: "memory")
#define CP_WAIT0()  asm volatile("cp.async.wait_group 0;" ::: "memory")
#define CP_WAIT1()  asm volatile("cp.async.wait_group 1;" ::: "memory")

__device__ __forceinline__ void ldsm4(uint32_t* r, uint32_t a) {
    asm volatile("ldmatrix.sync.aligned.m8n8.x4.shared.b16 {%0,%1,%2,%3}, [%4];"
        : "=r"(r[0]), "=r"(r[1]), "=r"(r[2]), "=r"(r[3]) : "r"(a));
}
__device__ __forceinline__ void mma16816(float* c, const uint32_t* a, uint32_t b0, uint32_t b1) {
    asm volatile("mma.sync.aligned.m16n8k16.row.col.f32.f16.f16.f32 "
        "{%0,%1,%2,%3}, {%4,%5,%6,%7}, {%8,%9}, {%0,%1,%2,%3};"
        : "+f"(c[0]), "+f"(c[1]), "+f"(c[2]), "+f"(c[3])
        : "r"(a[0]), "r"(a[1]), "r"(a[2]), "r"(a[3]), "r"(b0), "r"(b1));
}

// -------------------- input conversion kernels -----------------------------
__global__ __launch_bounds__(256) void conv_f16_kernel(
    const float* __restrict__ x, __half* __restrict__ h)
{
    int i = blockIdx.x * 256 + threadIdx.x;
    float4 v = ((const float4*)x)[i];
    __half2 h01 = __floats2half2_rn(v.x, v.y);
    __half2 h23 = __floats2half2_rn(v.z, v.w);
    ((__half2*)h)[2 * i]     = h01;
    ((__half2*)h)[2 * i + 1] = h23;
}

// W [K,N] row-major -> T [N,K] fp16
__global__ __launch_bounds__(256) void wtrans_kernel(
    const float* __restrict__ W, __half* __restrict__ Th, int K, int N)
{
    __shared__ float tile[32][33];
    const int bx = blockIdx.x, by = blockIdx.y;
    const int tx = threadIdx.x & 31, ty = threadIdx.x >> 5;
#pragma unroll
    for (int i = 0; i < 4; i++)
        tile[ty + i * 8][tx] = W[(size_t)(by * 32 + ty + i * 8) * N + bx * 32 + tx];
    __syncthreads();
#pragma unroll
    for (int i = 0; i < 4; i++) {
        float v = tile[tx][ty + i * 8];
        size_t o = (size_t)(bx * 32 + ty + i * 8) * K + by * 32 + tx;
        Th[o] = __float2half_rn(v);
    }
}

// bc[r*1024+n] = b1[n] + sum_k bexp[r*512+k] * W1[k,n]
__global__ __launch_bounds__(1024) void bias_fold_kernel(
    const float* __restrict__ bexp, const float* __restrict__ W1,
    const float* __restrict__ b1, float* __restrict__ bc)
{
    const int r = blockIdx.x;
    const int n = threadIdx.x;
    float acc = b1[n];
    for (int k = 0; k < 512; k++)
        acc += bexp[r * 512 + k] * W1[(size_t)k * 1024 + n];
    bc[r * 1024 + n] = acc;
}

// -------------------- fp16 mma.sync GEMM (generic, fp16 out) ---------------
template <bool RELU>
__global__ __launch_bounds__(256, 2) void gemm_f16(
    const __half* __restrict__ A, int lda,
    const __half* __restrict__ Bw, int ldb,
    const float* __restrict__ bias,
    __half* __restrict__ Ch,
    int M, int N, int K, int bzs, int czs)
{
    constexpr uint32_t OFF_B = 16384;
    constexpr uint32_t STAGE = 32768;
    extern __shared__ __align__(16) char dsm[];
    const uint32_t sbase = smem_u32(dsm);
    const int tid = threadIdx.x;
    const int lane = tid & 31, w = tid >> 5;
    const int z = blockIdx.z;
    const int m0 = blockIdx.y * 128;
    const int n0 = blockIdx.x * 128;
    const int wm0 = (w >> 1) * 32;
    const int wn0 = (w & 1) * 64;
    const int nch = K >> 6;

    const int lrow = tid >> 3;
    const int lcg  = tid & 7;
    const char* pA = (const char*)A;
    const char* pB = (const char*)Bw + (size_t)z * bzs * 2;

#define ISSUE(k0, sb_)                                                         \
    {                                                                          \
        uint32_t sb = (sb_);                                                   \
        _Pragma("unroll")                                                      \
        for (int j = 0; j < 4; j++) {                                          \
            int r = lrow + j * 32;                                             \
            uint32_t so = swz128((uint32_t)(r * 128 + lcg * 16));              \
            size_t goA = ((size_t)(m0 + r) * lda + (k0) + lcg * 8) * 2;        \
            size_t goB = ((size_t)(n0 + r) * ldb + (k0) + lcg * 8) * 2;        \
            cpa16(sb + so, pA + goA);                                          \
            cpa16(sb + OFF_B + so, pB + goB);                                  \
        }                                                                      \
    }

    float acc[2][8][4];
#pragma unroll
    for (int mt = 0; mt < 2; mt++)
#pragma unroll
        for (int nt = 0; nt < 8; nt++)
#pragma unroll
            for (int q = 0; q < 4; q++) acc[mt][nt][q] = 0.f;

    const uint32_t stg[3] = {sbase, sbase + STAGE, sbase + 2 * STAGE};

    ISSUE(0, stg[0]); CP_COMMIT();
    ISSUE(64, stg[1]); CP_COMMIT();

    const int rl = ((lane >> 3) & 1) * 8 + (lane & 7);
    const int kb = (lane >> 4) * 8;

    int cs = 0;
    int is2 = 2;
#pragma unroll 1
    for (int c = 0; c < nch; c++) {
        if (c == nch - 1) { CP_WAIT0(); } else { CP_WAIT1(); }
        __syncthreads();
        if (c + 2 < nch) {
            ISSUE((c + 2) << 6, stg[is2]); CP_COMMIT();
            if (++is2 == 3) is2 = 0;
        }

        const uint32_t a_b = stg[cs];
        const uint32_t b_b = a_b + OFF_B;
        if (++cs == 3) cs = 0;
#pragma unroll
        for (int ks = 0; ks < 4; ks++) {
            const uint32_t kof = (uint32_t)((ks * 16 + kb) * 2);
            uint32_t aH[2][4];
#pragma unroll
            for (int mt = 0; mt < 2; mt++) {
                uint32_t off = swz128((uint32_t)((wm0 + mt * 16 + rl) * 128) + kof);
                ldsm4(aH[mt], a_b + off);
            }
            uint32_t bH[4][4];
#pragma unroll
            for (int ng = 0; ng < 4; ng++) {
                uint32_t off = swz128((uint32_t)((wn0 + ng * 16 + rl) * 128) + kof);
                ldsm4(bH[ng], b_b + off);
            }
#pragma unroll
            for (int mt = 0; mt < 2; mt++)
#pragma unroll
                for (int nt = 0; nt < 8; nt++) {
                    const int ng = nt >> 1, sl = nt & 1;
                    mma16816(acc[mt][nt], aH[mt], bH[ng][sl], bH[ng][sl + 2]);
                }
        }
    }

#pragma unroll
    for (int mt = 0; mt < 2; mt++) {
#pragma unroll
        for (int nt = 0; nt < 8; nt++) {
            const int row = m0 + wm0 + mt * 16 + (lane >> 2);
            const int col = n0 + wn0 + nt * 8 + (lane & 3) * 2;
            float bv0 = __ldg(bias + col);
            float bv1 = __ldg(bias + col + 1);
            float v00 = acc[mt][nt][0] + bv0;
            float v01 = acc[mt][nt][1] + bv1;
            float v10 = acc[mt][nt][2] + bv0;
            float v11 = acc[mt][nt][3] + bv1;
            if (RELU) {
                v00 = fmaxf(v00, 0.f); v01 = fmaxf(v01, 0.f);
                v10 = fmaxf(v10, 0.f); v11 = fmaxf(v11, 0.f);
            }
            size_t g0 = (size_t)row * N + col + (size_t)z * czs;
            size_t g1 = (size_t)(row + 8) * N + col + (size_t)z * czs;
            *(__half2*)(Ch + g0) = __floats2half2_rn(v00, v01);
            *(__half2*)(Ch + g1) = __floats2half2_rn(v10, v11);
        }
    }
#undef ISSUE
}

// -------------------- fused GEMM3 + log-softmax + gather + msum ------------
// Block tile 64(M) x 512(N=V), 512 threads (4x4 warps, warp tile 16x128),
// K=1024, 3-stage cp.async. Epilogue: fp32 logits -> smem, per-row softmax,
// fp32 logprobs out, fp16 Pext gather, block-reduced Msum atomicAdd.
#define G3_OFFB  8192u
#define G3_STAGE 73728u   // A 8 KB + B 64 KB
#define G3_ROWP  516      // she row stride (floats)

__global__ __launch_bounds__(512, 1) void gemm3_softmax_kernel(
    const __half* __restrict__ A,      // H [65536,1024]
    const __half* __restrict__ Bw,     // W2t [512,1024]
    const float* __restrict__ bias,    // b2
    float* __restrict__ lp_out,
    __half* __restrict__ Pext,
    const int* __restrict__ targets,
    const int* __restrict__ olen,
    float* __restrict__ Msum)
{
    extern __shared__ __align__(16) char dsm[];
    const uint32_t sbase = smem_u32(dsm);
    float* she = (float*)dsm;                        // [64][516] (overlay)
    float* redsm = (float*)(dsm + 3 * G3_STAGE);     // [16]
    const int tid = threadIdx.x;
    const int lane = tid & 31, w = tid >> 5;
    const int wm0 = (w >> 2) * 16;    // 4 M-warps
    const int wn0 = (w & 3) * 128;    // 4 N-warps
    const int m0 = blockIdx.x * 64;
    const int b  = m0 >> 11;
    const int K = 1024;
    const int nch = 16;

    const int lr  = tid >> 3;         // 0..63
    const int lcg = tid & 7;
    const char* pA = (const char*)A;
    const char* pB = (const char*)Bw;

#define G3ISSUE(k0, sb_)                                                       \
    {                                                                          \
        uint32_t sb = (sb_);                                                   \
        {                                                                      \
            uint32_t so = swz128((uint32_t)(lr * 128 + lcg * 16));             \
            cpa16(sb + so, pA + ((size_t)(m0 + lr) * K + (k0) + lcg * 8) * 2); \
        }                                                                      \
        _Pragma("unroll")                                                      \
        for (int j = 0; j < 8; j++) {                                          \
            int n = lr + 64 * j;                                               \
            uint32_t so = swz128((uint32_t)(n * 128 + lcg * 16));              \
            cpa16(sb + G3_OFFB + so, pB + ((size_t)n * K + (k0) + lcg * 8) * 2); \
        }                                                                      \
    }

    float acc[16][4];
#pragma unroll
    for (int nt = 0; nt < 16; nt++)
#pragma unroll
        for (int q = 0; q < 4; q++) acc[nt][q] = 0.f;

    const uint32_t stg[3] = {sbase, sbase + G3_STAGE, sbase + 2 * G3_STAGE};

    G3ISSUE(0, stg[0]); CP_COMMIT();
    G3ISSUE(64, stg[1]); CP_COMMIT();

    const int rl = ((lane >> 3) & 1) * 8 + (lane & 7);
    const int kb = (lane >> 4) * 8;

    int cs = 0;
    int is2 = 2;
#pragma unroll 1
    for (int c = 0; c < nch; c++) {
        if (c == nch - 1) { CP_WAIT0(); } else { CP_WAIT1(); }
        __syncthreads();
        if (c + 2 < nch) {
            G3ISSUE((c + 2) << 6, stg[is2]); CP_COMMIT();
            if (++is2 == 3) is2 = 0;
        }

        const uint32_t a_b = stg[cs];
        const uint32_t b_b = a_b + G3_OFFB;
        if (++cs == 3) cs = 0;
#pragma unroll
        for (int ks = 0; ks < 4; ks++) {
            const uint32_t kof = (uint32_t)((ks * 16 + kb) * 2);
            uint32_t aH[4];
            ldsm4(aH, a_b + swz128((uint32_t)((wm0 + rl) * 128) + kof));
            uint32_t bH[8][4];
#pragma unroll
            for (int ng = 0; ng < 8; ng++)
                ldsm4(bH[ng], b_b + swz128((uint32_t)((wn0 + ng * 16 + rl) * 128) + kof));
#pragma unroll
            for (int nt = 0; nt < 16; nt++) {
                const int ng = nt >> 1, sl = nt & 1;
                mma16816(acc[nt], aH, bH[ng][sl], bH[ng][sl + 2]);
            }
        }
    }
    __syncthreads();   // pipeline smem now dead; she overlay begins

    // stage logits (+bias) to smem, fp32
    const int r0 = lane >> 2;
#pragma unroll
    for (int nt = 0; nt < 16; nt++) {
        int col = wn0 + nt * 8 + (lane & 3) * 2;
        float bv0 = __ldg(bias + col);
        float bv1 = __ldg(bias + col + 1);
        she[(wm0 + r0) * G3_ROWP + col]         = acc[nt][0] + bv0;
        she[(wm0 + r0) * G3_ROWP + col + 1]     = acc[nt][1] + bv1;
        she[(wm0 + r0 + 8) * G3_ROWP + col]     = acc[nt][2] + bv0;
        she[(wm0 + r0 + 8) * G3_ROWP + col + 1] = acc[nt][3] + bv1;
    }
    __syncthreads();

    // per-row softmax: warp w owns rows 4w..4w+3
    const int* tg = targets + b * L_;
    const int inb = __ldg(olen + b);
    float msum_acc = 0.f;
#pragma unroll 1
    for (int rr = 0; rr < 4; rr++) {
        const int row = 4 * w + rr;
        float* sr = she + row * G3_ROWP;
        float v[16];
#pragma unroll
        for (int i = 0; i < 16; i++) v[i] = sr[lane + 32 * i];
        float mx = v[0];
#pragma unroll
        for (int i = 1; i < 16; i++) mx = fmaxf(mx, v[i]);
        mx = warpReduceMaxF(mx);
        float e[16];
        float sm = 0.f;
#pragma unroll
        for (int i = 0; i < 16; i++) { e[i] = __expf(v[i] - mx); sm += e[i]; }
        sm = warpReduceSumF(sm);
        float lse = __logf(sm);
        float* lpr = lp_out + (size_t)(m0 + row) * V_;
#pragma unroll
        for (int i = 0; i < 16; i++) lpr[lane + 32 * i] = v[i] - mx - lse;
#pragma unroll
        for (int i = 0; i < 16; i++) sr[lane + 32 * i] = e[i];
        __syncwarp();
        float pm = 0.f;
        for (int s = lane; s < S_; s += 32) {
            int lab = (s & 1) ? tg[s >> 1] : 1;
            pm = fmaxf(pm, sr[lab]);
        }
        pm = warpReduceMaxF(pm);
        float inv = 1.0f / pm;
        __half* Pr = Pext + (size_t)(m0 + row) * SP_;
        for (int s = lane; s < S_; s += 32) {
            int lab = (s & 1) ? tg[s >> 1] : 1;
            Pr[s] = __float2half_rn(sr[lab] * inv);
        }
        int trow = (m0 + row) & (T_ - 1);
        if (lane == 0 && trow < inb) msum_acc += __logf(pm) - lse;
    }
    if (lane == 0) redsm[w] = msum_acc;
    __syncthreads();
    if (tid == 0) {
        float r = 0.f;
#pragma unroll
        for (int i = 0; i < 16; i++) r += redsm[i];
        atomicAdd(&Msum[b], r);
    }
#undef G3ISSUE
}

// -------------------- lengths (also zeroes Msum) ----------------------------
__global__ __launch_bounds__(256) void lengths_kernel(
    const int* __restrict__ encm, const int* __restrict__ tgtm,
    float* __restrict__ out, int len_off, int loss_off,
    int* __restrict__ tlen, int* __restrict__ olen, float* __restrict__ Msum)
{
    const int b = blockIdx.x, tid = threadIdx.x;
    const int lane = tid & 31, wid = tid >> 5;
    int c1 = 0;
    for (int i = tid; i < SSRC; i += 256) c1 += (encm[b * SSRC + i] != 0);
    int c2 = 0;
    for (int i = tid; i < L_; i += 256) c2 += (tgtm[b * L_ + i] != 0);
    c1 = warpReduceSumI(c1);
    c2 = warpReduceSumI(c2);
    __shared__ int redi[16];
    if (lane == 0) { redi[wid] = c1; redi[8 + wid] = c2; }
    __syncthreads();
    if (tid == 0) {
        int a = 0, t = 0;
#pragma unroll
        for (int i = 0; i < 8; i++) { a += redi[i]; t += redi[8 + i]; }
        olen[b] = STR_ * a;
        tlen[b] = t;
        Msum[b] = 0.f;
        out[len_off + b] = (float)(STR_ * a);
        if (b == 0) out[loss_off] = 0.f;
    }
}

// -------------------- CTC forward DP (2 steps per barrier) ------------------
__global__ __launch_bounds__(544) void ctc_dp_kernel(
    const __half* __restrict__ Pext, const float* __restrict__ Msum,
    const int* __restrict__ targets, const int* __restrict__ tlen,
    const int* __restrict__ olen, float* __restrict__ loss_slot)
{
    const int b = blockIdx.x;
    const int tid = threadIdx.x;
    __shared__ float sA[548], sB[548];
    __shared__ __align__(16) __half bufh[2][CH_][SP_];
    __shared__ float warpred[17];
    __shared__ float s_inv;

    const int s = tid;
    const bool active = (s < S_);
    const int inlen = olen[b];
    const int tl = tlen[b];

    bool k0 = false, k1 = false, k2 = false;
    {
        const int* tg = targets + b * L_;
#define SKIPAT(x, out)                                                        \
        if ((x) >= 1 && ((x) & 1)) {                                          \
            int l = (x) >> 1;                                                 \
            int tc = tg[l];                                                   \
            out = (tc != 1) && (l == 0 || tc != tg[l - 1]);                   \
        }
        if (active) { SKIPAT(s, k0); SKIPAT(s - 1, k1); SKIPAT(s - 2, k2); }
#undef SKIPAT
    }

    sA[tid] = 0.f; sB[tid] = 0.f;
    if (tid < 4) { sA[544 + tid] = 0.f; sB[544 + tid] = 0.f; }

    const __half* Pb = Pext + (size_t)b * T_ * SP_;
    {
        const int li0 = tid, li1 = tid + 544;
        uint4 r0, r1;
        if (li0 < 1040) r0 = ((const uint4*)Pb)[li0];
        if (li1 < 1040) r1 = ((const uint4*)Pb)[li1];
        if (li0 < 1040) ((uint4*)&bufh[0][0][0])[li0] = r0;
        if (li1 < 1040) ((uint4*)&bufh[0][0][0])[li1] = r1;
    }
    __syncthreads();

    float* cur = sA;
    float* nxt = sB;
    if (active) {
        float P0 = __half2float(bufh[0][0][s]);
        cur[4 + s] = (s == 0 || (s == 1 && tl > 0)) ? P0 : 0.f;
    }
    __syncthreads();

    const int sm1 = (s >= 1) ? s - 1 : 0;
    const int sm2 = (s >= 2) ? s - 2 : 0;

    float Cacc = 0.f;
    uint4 rp;
    const bool ldact = (tid < 520);
#pragma unroll 1
    for (int c = 0; c < NC_; c++) {
        if (c + 2 < NC_ && ldact)
            rp = ((const uint4*)(Pb + (size_t)(c + 2) * CH_ * SP_))[tid];
        const int cb = c & 1;
#pragma unroll
        for (int q = 0; q < 4; q++) {
            const int t1 = 8 * c + 2 * q + 1;
            const int t2 = t1 + 1;
            if (active) {
                float a0 = cur[4 + s];
                float a1 = cur[3 + s];
                float a2 = cur[2 + s];
                float a3 = cur[1 + s];
                float a4 = cur[s];
                const __half* row1 = &bufh[cb][2 * q + 1][0];
                float P1s  = __half2float(row1[s]);
                float P1m1 = __half2float(row1[sm1]);
                float P1m2 = __half2float(row1[sm2]);
                float P2s  = (q < 3) ? __half2float(bufh[cb][2 * q + 2][s])
                                     : __half2float(bufh[cb ^ 1][0][s]);
                bool fr1 = (t1 >= inlen);
                bool fr2 = (t2 >= inlen);
                float v1s  = fr1 ? a0 : (a0 + a1 + (k0 ? a2 : 0.f)) * P1s;
                float v1m1 = fr1 ? a1 : (a1 + a2 + (k1 ? a3 : 0.f)) * P1m1;
                float v1m2 = fr1 ? a2 : (a2 + a3 + (k2 ? a4 : 0.f)) * P1m2;
                float v2s  = fr2 ? v1s : (v1s + v1m1 + (k0 ? v1m2 : 0.f)) * P2s;
                nxt[4 + s] = v2s;
            }
            __syncthreads();
            { float* tmp = cur; cur = nxt; nxt = tmp; }
        }
        if (c + 2 < NC_ && ldact)
            ((uint4*)&bufh[cb][0][0])[tid] = rp;
        if (cb == 1) {
            float mv = active ? cur[4 + s] : 0.f;
            mv = warpReduceMaxF(mv);
            if ((tid & 31) == 0) warpred[tid >> 5] = mv;
            __syncthreads();
            if (tid == 0) {
                float r = warpred[0];
#pragma unroll
                for (int i = 1; i < 17; i++) r = fmaxf(r, warpred[i]);
                if (r > 0.f) { s_inv = 1.0f / r; Cacc += __logf(r); }
                else s_inv = 1.0f;
            }
            __syncthreads();
            if (active) cur[4 + s] *= s_inv;
            __syncthreads();
        }
    }

    if (tid == 0) {
        int il2 = 2 * tl;
        float al = cur[4 + il2];
        float ap = (tl > 0) ? cur[3 + il2] : 0.f;
        float per = -(__logf(al + ap) + Cacc + Msum[b]);
        float tld = (float)(tl > 0 ? tl : 1);
        atomicAdd(loss_slot, per / (tld * (float)B_));
    }
}

__global__ void finalize_kernel(float* out, int loss_off)
{
    float v = out[loss_off];
    if (!isfinite(v)) out[loss_off] = 0.f;
}

// -------------------- launch ------------------------------------------------
extern "C" void kernel_launch(void* const* d_in, const int* in_sizes, int n_in,
                              void* d_out, int out_size)
{
    const float* rep  = (const float*)d_in[0];
    const int*   encm = (const int*)d_in[1];
    const int*   tgt  = (const int*)d_in[2];
    const int*   tgtm = (const int*)d_in[3];
    const float* Wexp = (const float*)d_in[4];
    const float* bexp = (const float*)d_in[5];
    const float* W1   = (const float*)d_in[6];
    const float* b1   = (const float*)d_in[7];
    const float* W2   = (const float*)d_in[8];
    const float* b2   = (const float*)d_in[9];
    float* out = (float*)d_out;

    __half *p_repf, *p_Wexpf, *p_W1t, *p_W2t, *p_Bc, *p_H, *p_Pexth;
    float *p_bc, *p_zb, *p_Msum;
    int *p_tlen, *p_olen;
    cudaGetSymbolAddress((void**)&p_repf, g_repf);
    cudaGetSymbolAddress((void**)&p_Wexpf, g_Wexpf);
    cudaGetSymbolAddress((void**)&p_W1t, g_W1t);
    cudaGetSymbolAddress((void**)&p_W2t, g_W2t);
    cudaGetSymbolAddress((void**)&p_Bc, g_Bc);
    cudaGetSymbolAddress((void**)&p_bc, g_bc);
    cudaGetSymbolAddress((void**)&p_zb, g_zb);
    cudaGetSymbolAddress((void**)&p_H, g_H);
    cudaGetSymbolAddress((void**)&p_Pexth, g_Pexth);
    cudaGetSymbolAddress((void**)&p_Msum, g_Msum);
    cudaGetSymbolAddress((void**)&p_tlen, g_tlen);
    cudaGetSymbolAddress((void**)&p_olen, g_olen);

    const int SMEM_GEMM = 3 * 32768;              // 96 KB -> occ 2
    const int SMEM_G3   = 3 * (int)G3_STAGE + 256; // 216 KB + red
    cudaFuncSetAttribute(gemm_f16<false>, cudaFuncAttributeMaxDynamicSharedMemorySize, SMEM_GEMM);
    cudaFuncSetAttribute(gemm_f16<true >, cudaFuncAttributeMaxDynamicSharedMemorySize, SMEM_GEMM);
    cudaFuncSetAttribute(gemm3_softmax_kernel, cudaFuncAttributeMaxDynamicSharedMemorySize, SMEM_G3);

    // conversions
    conv_f16_kernel<<<8192, 256>>>(rep, p_repf);           // 16384x512
    conv_f16_kernel<<<1024, 256>>>(Wexp, p_Wexpf);         // 512x2048
    wtrans_kernel<<<dim3(1024 / 32, 512 / 32), 256>>>(W1, p_W1t, 512, 1024);
    wtrans_kernel<<<dim3(512 / 32, 1024 / 32), 256>>>(W2, p_W2t, 1024, 512);
    bias_fold_kernel<<<4, 1024>>>(bexp, W1, b1, p_bc);

    // merged weight Bc: single launch, blockIdx.z = r
    gemm_f16<false><<<dim3(4, 8, 4), 256, SMEM_GEMM>>>(
        p_W1t, 512, p_Wexpf, 2048, p_zb,
        p_Bc, 1024, 512, 512, /*bzs=*/512, /*czs=*/1024 * 512);

    // merged GEMM: H[16384,4096] = relu(rep @ Bc^T + bc)  (fp16 out)
    gemm_f16<true><<<dim3(32, 128, 1), 256, SMEM_GEMM>>>(
        p_repf, 512, p_Bc, 512, p_bc, p_H, 16384, 4096, 512, 0, 0);

    const int loss_off = out_size - 1;
    const int len_off  = out_size - 1 - B_;
    lengths_kernel<<<B_, 256>>>(encm, tgtm, out, len_off, loss_off, p_tlen, p_olen, p_Msum);

    // fused GEMM3 + softmax + gather + msum
    gemm3_softmax_kernel<<<1024, 512, SMEM_G3>>>(
        p_H, p_W2t, b2, out, p_Pexth, tgt, p_olen, p_Msum);

    ctc_dp_kernel<<<B_, 544>>>(p_Pexth, p_Msum, tgt, p_tlen, p_olen, out + loss_off);
    finalize_kernel<<<1, 1>>>(out, loss_off);
}